// round 1
// baseline (speedup 1.0000x reference)
#include <cuda_runtime.h>
#include <cuda_bf16.h>
#include <float.h>

// BinsChamferLoss: sum over (b, p) of min_t | center(b,p) - target(b,t) |
// targets masked: t = (t >= 0.001) ? t : 0.0  (masked values remain valid targets)
//
// Algorithm (exact, O(M log P) instead of O(P*M)):
//   1) centers = 0.5*(bins[:,1:]+bins[:,:-1]); sort 256 centers per batch (bitonic).
//   2) scatter: each target finds its bracketing centers by binary search;
//      records itself via atomicMax (as "candidate predecessor" for the center
//      just above it) and atomicMin ("candidate successor" for the center just
//      below it). Nonnegative float bits are order-isomorphic to signed ints.
//   3) prefix-max / suffix-min over the 256 slots => exact pred/succ per center.
//      distance = min(c - pred, succ - c), with +inf sentinels matching the
//      reference's clamped searchsorted behavior.
//   4) deterministic per-batch sums, single-thread final sum.

#define MAXB 32
#define P_BINS 256
#define MIN_DEPTH 0.001f
#define SPLITS 32           // blocks per batch in the scatter kernel

__device__ float g_centers[MAXB * P_BINS];
__device__ int   g_maxBelow[MAXB * P_BINS];  // int-encoded float bits; INT_MIN = none
__device__ int   g_minAbove[MAXB * P_BINS];  // int-encoded float bits; INT_MAX = none
__device__ float g_batchSum[MAXB];

// ---------------- Kernel 1: centers + bitonic sort + scratch init ----------
__global__ void k_centers_sort(const float* __restrict__ bins)
{
    const int b   = blockIdx.x;
    const int tid = threadIdx.x;

    __shared__ float s[P_BINS];
    const float* bb = bins + b * (P_BINS + 1);
    s[tid] = 0.5f * (bb[tid] + bb[tid + 1]);
    __syncthreads();

    // Bitonic sort 256 elements with 256 threads
    for (int k = 2; k <= P_BINS; k <<= 1) {
        for (int j = k >> 1; j > 0; j >>= 1) {
            int ixj = tid ^ j;
            if (ixj > tid) {
                float a = s[tid], c = s[ixj];
                bool up = ((tid & k) == 0);
                if ((a > c) == up) { s[tid] = c; s[ixj] = a; }
            }
            __syncthreads();
        }
    }

    g_centers[b * P_BINS + tid]  = s[tid];
    g_maxBelow[b * P_BINS + tid] = INT_MIN;
    g_minAbove[b * P_BINS + tid] = INT_MAX;
}

// ---------------- Kernel 2: target scatter -------------------------------
__global__ void k_scatter(const float* __restrict__ depth, int M)
{
    const int b   = blockIdx.y;
    const int tid = threadIdx.x;

    __shared__ float sC[P_BINS];
    __shared__ int   sMaxB[P_BINS];
    __shared__ int   sMinA[P_BINS];

    sC[tid]    = g_centers[b * P_BINS + tid];
    sMaxB[tid] = INT_MIN;
    sMinA[tid] = INT_MAX;
    __syncthreads();

    const float4* tgt4 = (const float4*)(depth + (long long)b * M);
    const int M4 = M >> 2;                    // M divisible by 4 (76800)
    const int stride = gridDim.x * blockDim.x;

    for (int i = blockIdx.x * blockDim.x + tid; i < M4; i += stride) {
        float4 v = tgt4[i];
        float vals[4] = {v.x, v.y, v.z, v.w};
#pragma unroll
        for (int q = 0; q < 4; ++q) {
            float t = vals[q];
            t = (t >= MIN_DEPTH) ? t : 0.0f;  // masked pixels become target 0.0
            int tb = __float_as_int(t);       // t >= 0 -> monotone int encoding

            // lower_bound: first center >= t  (t is a predecessor candidate there)
            int lo = 0, hi = P_BINS;
            while (lo < hi) { int mid = (lo + hi) >> 1; if (sC[mid] <  t) lo = mid + 1; else hi = mid; }
            if (lo < P_BINS) atomicMax(&sMaxB[lo], tb);

            // upper_bound - 1: last center <= t  (t is a successor candidate there)
            lo = 0; hi = P_BINS;
            while (lo < hi) { int mid = (lo + hi) >> 1; if (sC[mid] <= t) lo = mid + 1; else hi = mid; }
            if (lo > 0) atomicMin(&sMinA[lo - 1], tb);
        }
    }
    __syncthreads();

    if (sMaxB[tid] != INT_MIN) atomicMax(&g_maxBelow[b * P_BINS + tid], sMaxB[tid]);
    if (sMinA[tid] != INT_MAX) atomicMin(&g_minAbove[b * P_BINS + tid], sMinA[tid]);
}

// ---------------- Kernel 3: prefix/suffix + per-batch sum ----------------
__global__ void k_reduce_batch()
{
    const int b   = blockIdx.x;
    const int tid = threadIdx.x;

    __shared__ int   sp[P_BINS];   // prefix max of maxBelow
    __shared__ int   ss[P_BINS];   // suffix min of minAbove
    __shared__ float sr[P_BINS];

    sp[tid] = g_maxBelow[b * P_BINS + tid];
    ss[tid] = g_minAbove[b * P_BINS + tid];
    __syncthreads();

    for (int off = 1; off < P_BINS; off <<= 1) {
        int vp = sp[tid];
        int vs = ss[tid];
        if (tid >= off)           vp = max(vp, sp[tid - off]);
        if (tid + off < P_BINS)   vs = min(vs, ss[tid + off]);
        __syncthreads();
        sp[tid] = vp;
        ss[tid] = vs;
        __syncthreads();
    }

    float c = g_centers[b * P_BINS + tid];
    float dLo = (sp[tid] == INT_MIN) ? FLT_MAX : (c - __int_as_float(sp[tid]));
    float dHi = (ss[tid] == INT_MAX) ? FLT_MAX : (__int_as_float(ss[tid]) - c);
    sr[tid] = fminf(dLo, dHi);
    __syncthreads();

    for (int off = P_BINS >> 1; off > 0; off >>= 1) {
        if (tid < off) sr[tid] += sr[tid + off];
        __syncthreads();
    }
    if (tid == 0) g_batchSum[b] = sr[0];
}

// ---------------- Kernel 4: final deterministic sum ----------------------
__global__ void k_final(float* __restrict__ out, int B)
{
    if (threadIdx.x == 0) {
        float s = 0.0f;
        for (int b = 0; b < B; ++b) s += g_batchSum[b];
        out[0] = s;
    }
}

extern "C" void kernel_launch(void* const* d_in, const int* in_sizes, int n_in,
                              void* d_out, int out_size)
{
    // Identify inputs by size: bins is the small one (B*(P+1)), depth the large.
    int bi = 0, di = 1;
    if (n_in >= 2 && in_sizes[0] > in_sizes[1]) { bi = 1; di = 0; }
    const float* bins  = (const float*)d_in[bi];
    const float* depth = (const float*)d_in[di];

    const int B = in_sizes[bi] / (P_BINS + 1);
    const int M = in_sizes[di] / B;

    k_centers_sort<<<B, P_BINS>>>(bins);
    dim3 grid2(SPLITS, B);
    k_scatter<<<grid2, P_BINS>>>(depth, M);
    k_reduce_batch<<<B, P_BINS>>>();
    k_final<<<1, 32>>>((float*)d_out, B);
}

// round 4
// speedup vs baseline: 1.2145x; 1.2145x over previous
#include <cuda_runtime.h>
#include <cuda_bf16.h>
#include <float.h>

// BinsChamferLoss, single fused kernel.
// sum over (b,p) of min_t | center(b,p) - target(b,t) |, targets masked to 0 below 0.001.
//
// Per block (grid = SPLITS x B, 256 threads):
//   1) bitonic-sort the batch's 256 bin centers in smem (redundant per block; cheap)
//   2) scatter its slice of targets: one binary search per target finds the
//      bracketing centers; smem atomicMax with order-preserving u32 encodings
//      records best predecessor/successor candidates per center slot
//   3) flush smem candidates to global scratch (zero = "none" sentinel, so the
//      zero-initialized __device__ arrays are valid initial state)
//   4) last block per batch: prefix-max/suffix-min over the 256 slots -> exact
//      pred/succ per center -> per-batch sum; resets scratch for graph replay
//   5) last batch-finisher: fixed-order sum of batch sums -> out[0]
//
// Encodings (targets are >= 0, so float bits are order-isomorphic to u32):
//   maxBelow: enc = bits(t) + 1      (u32 atomicMax; 0 = none)
//   minAbove: enc = ~bits(t)         (u32 atomicMax == min over t; 0 = none)

#define MAXB 32
#define P_BINS 256
#define MIN_DEPTH 0.001f
#define SPLITS 32

__device__ unsigned int g_maxBelow[MAXB * P_BINS];   // zero-init = "none"
__device__ unsigned int g_minAbove[MAXB * P_BINS];   // zero-init = "none"
__device__ float        g_batchSum[MAXB];
__device__ unsigned int g_cnt[MAXB];                 // per-batch arrival counters
__device__ unsigned int g_done;                      // batch-finisher counter

__global__ void __launch_bounds__(P_BINS)
k_fused(const float* __restrict__ bins, const float* __restrict__ depth,
        int M, int B, float* __restrict__ out)
{
    const int b   = blockIdx.y;
    const int tid = threadIdx.x;

    __shared__ float        sC[P_BINS];
    __shared__ unsigned int sA[P_BINS];   // maxBelow candidates (enc)
    __shared__ unsigned int sS[P_BINS];   // minAbove candidates (enc)
    __shared__ int          sFinisher;

    // ---- Phase 1: centers + bitonic sort (each block does its batch) ----
    {
        const float* bb = bins + b * (P_BINS + 1);
        sC[tid] = 0.5f * (bb[tid] + bb[tid + 1]);
        sA[tid] = 0u;
        sS[tid] = 0u;
    }
    __syncthreads();

    for (int k = 2; k <= P_BINS; k <<= 1) {
        for (int j = k >> 1; j > 0; j >>= 1) {
            int ixj = tid ^ j;
            if (ixj > tid) {
                float a = sC[tid], c = sC[ixj];
                bool up = ((tid & k) == 0);
                if ((a > c) == up) { sC[tid] = c; sC[ixj] = a; }
            }
            __syncthreads();
        }
    }

    // ---- Phase 2: scatter this block's target slice ----
    {
        const float4* tgt4 = (const float4*)(depth + (long long)b * M);
        const int M4 = M >> 2;                         // M % 4 == 0
        const int stride = gridDim.x * blockDim.x;

        for (int i = blockIdx.x * blockDim.x + tid; i < M4; i += stride) {
            float4 v = tgt4[i];
            float vals[4] = {v.x, v.y, v.z, v.w};
#pragma unroll
            for (int q = 0; q < 4; ++q) {
                float t = vals[q];
                t = (t >= MIN_DEPTH) ? t : 0.0f;
                unsigned int tb = __float_as_uint(t);

                // lower_bound: first center >= t.  257 possible answers ->
                // NEEDS 9 halving steps (8 was the R2 bug). 9th is guarded.
                int lo = 0, hi = P_BINS;
#pragma unroll
                for (int s = 0; s < 9; ++s) {
                    if (lo < hi) {
                        int mid = (lo + hi) >> 1;
                        if (sC[mid] < t) lo = mid + 1; else hi = mid;
                    }
                }
                if (lo < P_BINS) atomicMax(&sA[lo], tb + 1u);

                // upper_bound via tie-walk (ties ~never occur; stays exact)
                int ub = lo;
                while (ub < P_BINS && sC[ub] == t) ++ub;
                if (ub > 0) atomicMax(&sS[ub - 1], ~tb);
            }
        }
    }
    __syncthreads();

    // ---- Phase 3: flush to global scratch ----
    {
        unsigned int a = sA[tid], s = sS[tid];
        if (a) atomicMax(&g_maxBelow[b * P_BINS + tid], a);
        if (s) atomicMax(&g_minAbove[b * P_BINS + tid], s);
    }

    // ---- Phase 4: last block of this batch reduces it ----
    __threadfence();
    if (tid == 0) {
        unsigned int old = atomicAdd(&g_cnt[b], 1u);
        sFinisher = (old == (unsigned)(gridDim.x - 1));
    }
    __syncthreads();
    if (!sFinisher) return;
    __threadfence();   // acquire: make all batch-b blocks' flushes visible

    // Atomic reads (RMW with identity) of the scatter results.
    unsigned int encA = atomicMax(&g_maxBelow[b * P_BINS + tid], 0u);
    unsigned int encS = atomicMax(&g_minAbove[b * P_BINS + tid], 0u);
    // Reset scratch + counter for the next graph replay.
    g_maxBelow[b * P_BINS + tid] = 0u;
    g_minAbove[b * P_BINS + tid] = 0u;
    if (tid == 0) g_cnt[b] = 0u;

    sA[tid] = encA;
    sS[tid] = encS;
    __syncthreads();

    // prefix-max over sA, suffix-max over sS (both in encoded domain)
    for (int off = 1; off < P_BINS; off <<= 1) {
        unsigned int vp = sA[tid];
        unsigned int vs = sS[tid];
        if (tid >= off)         vp = max(vp, sA[tid - off]);
        if (tid + off < P_BINS) vs = max(vs, sS[tid + off]);
        __syncthreads();
        sA[tid] = vp;
        sS[tid] = vs;
        __syncthreads();
    }

    float c  = sC[tid];
    unsigned int pe = sA[tid], se = sS[tid];
    float dLo = pe ? (c - __uint_as_float(pe - 1u)) : FLT_MAX;
    float dHi = se ? (__uint_as_float(~se) - c)     : FLT_MAX;
    float d = fminf(dLo, dHi);
    __syncthreads();
    sC[tid] = d;
    __syncthreads();
    for (int off = P_BINS >> 1; off > 0; off >>= 1) {
        if (tid < off) sC[tid] += sC[tid + off];
        __syncthreads();
    }
    if (tid == 0) g_batchSum[b] = sC[0];

    // ---- Phase 5: last batch-finisher writes the final sum ----
    __threadfence();
    if (tid == 0) {
        unsigned int old = atomicAdd(&g_done, 1u);
        if (old == (unsigned)(B - 1)) {
            __threadfence();   // acquire other batches' g_batchSum writes
            float s = 0.0f;
            for (int i = 0; i < B; ++i) s += g_batchSum[i];
            out[0] = s;
            g_done = 0u;   // reset for next replay
        }
    }
}

extern "C" void kernel_launch(void* const* d_in, const int* in_sizes, int n_in,
                              void* d_out, int out_size)
{
    int bi = 0, di = 1;
    if (n_in >= 2 && in_sizes[0] > in_sizes[1]) { bi = 1; di = 0; }
    const float* bins  = (const float*)d_in[bi];
    const float* depth = (const float*)d_in[di];

    const int B = in_sizes[bi] / (P_BINS + 1);
    const int M = in_sizes[di] / B;

    dim3 grid(SPLITS, B);
    k_fused<<<grid, P_BINS>>>(bins, depth, M, B, (float*)d_out);
}

// round 5
// speedup vs baseline: 1.5496x; 1.2759x over previous
#include <cuda_runtime.h>
#include <cuda_bf16.h>
#include <float.h>

// BinsChamferLoss, single fused kernel (R5: occupancy + chain-length attack).
// sum over (b,p) of min_t | center(b,p) - target(b,t) |, targets masked to 0 below 0.001.
//
// Encodings (targets >= 0 -> float bits order-isomorphic to u32):
//   maxBelow: enc = bits(t) + 1   (u32 atomicMax; 0 = none)
//   minAbove: enc = ~bits(t)      (u32 atomicMax == min over t; 0 = none)

#define MAXB 32
#define P_BINS 256
#define MIN_DEPTH 0.001f
#define SPLITS 64

__device__ unsigned int g_maxBelow[MAXB * P_BINS];   // zero-init = "none"
__device__ unsigned int g_minAbove[MAXB * P_BINS];   // zero-init = "none"
__device__ float        g_batchSum[MAXB];
__device__ unsigned int g_cnt[MAXB];
__device__ unsigned int g_done;

__global__ void __launch_bounds__(P_BINS)
k_fused(const float* __restrict__ bins, const float* __restrict__ depth,
        int M, int B, float* __restrict__ out)
{
    const int b    = blockIdx.y;
    const int tid  = threadIdx.x;
    const int lane = tid & 31;
    const int warp = tid >> 5;

    __shared__ float        sC[P_BINS];
    __shared__ unsigned int sA[P_BINS];
    __shared__ unsigned int sS[P_BINS];
    __shared__ unsigned int wA[8], wS[8];
    __shared__ float        wsum[8];
    __shared__ int          sFinisher;

    // ---- Phase 1: centers + register bitonic sort (shfl for j<32) ----
    float v;
    {
        const float* bb = bins + b * (P_BINS + 1);
        v = 0.5f * (bb[tid] + bb[tid + 1]);
        sA[tid] = 0u;
        sS[tid] = 0u;
    }

#pragma unroll
    for (int k = 2; k <= P_BINS; k <<= 1) {
#pragma unroll
        for (int j = k >> 1; j >= 1; j >>= 1) {
            bool up = ((tid & k) == 0);
            float other;
            if (j >= 32) {
                __syncthreads();
                sC[tid] = v;
                __syncthreads();
                other = sC[tid ^ j];
            } else {
                other = __shfl_xor_sync(0xffffffffu, v, j);
            }
            bool lower = ((tid & j) == 0);
            v = (lower == up) ? fminf(v, other) : fmaxf(v, other);
        }
    }
    __syncthreads();
    sC[tid] = v;
    __syncthreads();

    // Register pivots for the first 3 search levels
    const float P127 = sC[127];
    const float P63  = sC[63],  P191 = sC[191];
    const float P31  = sC[31],  P95  = sC[95], P159 = sC[159], P223 = sC[223];

    // ---- Phase 2: scatter this block's target slice ----
    {
        const float4* tgt4 = (const float4*)(depth + (long long)b * M);
        const int M4 = M >> 2;                       // M % 4 == 0
        const int stride = gridDim.x * blockDim.x;

        for (int i = blockIdx.x * blockDim.x + tid; i < M4; i += stride) {
            float4 vv = tgt4[i];
            float vals[4] = {vv.x, vv.y, vv.z, vv.w};
#pragma unroll
            for (int q = 0; q < 4; ++q) {
                float t = vals[q];
                t = (t >= MIN_DEPTH) ? t : 0.0f;
                unsigned int tb = __float_as_uint(t);

                // branchless lower_bound: first 3 levels from registers
                int base = 0;
                if (P127 < t) base = 128;
                {
                    float p2 = (base == 128) ? P191 : P63;
                    if (p2 < t) base += 64;
                }
                {
                    float p3 = (base & 64) ? ((base & 128) ? P223 : P95)
                                           : ((base & 128) ? P159 : P31);
                    if (p3 < t) base += 32;
                }
#pragma unroll
                for (int step = 16; step >= 1; step >>= 1) {
                    if (sC[base + step - 1] < t) base += step;
                }
                if (sC[base] < t) base += 1;       // final correction -> lower_bound

                if (base < P_BINS) atomicMax(&sA[base], tb + 1u);

                // upper_bound via tie-walk (ties ~never; stays exact)
                int ub = base;
                while (ub < P_BINS && sC[ub] == t) ++ub;
                if (ub > 0) atomicMax(&sS[ub - 1], ~tb);
            }
        }
    }
    __syncthreads();

    // ---- Phase 3: flush to global scratch ----
    {
        unsigned int a = sA[tid], s = sS[tid];
        if (a) atomicMax(&g_maxBelow[b * P_BINS + tid], a);
        if (s) atomicMax(&g_minAbove[b * P_BINS + tid], s);
    }

    // ---- Phase 4: last block of this batch reduces it ----
    __threadfence();
    if (tid == 0) {
        unsigned int old = atomicAdd(&g_cnt[b], 1u);
        sFinisher = (old == (unsigned)(gridDim.x - 1));
    }
    __syncthreads();
    if (!sFinisher) return;
    __threadfence();   // acquire all batch-b flushes

    unsigned int encA = atomicMax(&g_maxBelow[b * P_BINS + tid], 0u);
    unsigned int encS = atomicMax(&g_minAbove[b * P_BINS + tid], 0u);
    g_maxBelow[b * P_BINS + tid] = 0u;     // reset for graph replay
    g_minAbove[b * P_BINS + tid] = 0u;
    if (tid == 0) g_cnt[b] = 0u;

    // prefix-max scan over encA (tid order), shuffle-based
    unsigned int pv = encA;
#pragma unroll
    for (int o = 1; o < 32; o <<= 1) {
        unsigned int n = __shfl_up_sync(0xffffffffu, pv, o);
        if (lane >= o) pv = max(pv, n);
    }
    if (lane == 31) wA[warp] = pv;

    // suffix-max scan over encS, shuffle-based
    unsigned int sv = encS;
#pragma unroll
    for (int o = 1; o < 32; o <<= 1) {
        unsigned int n = __shfl_down_sync(0xffffffffu, sv, o);
        if (lane + o < 32) sv = max(sv, n);
    }
    if (lane == 0) wS[warp] = sv;
    __syncthreads();

    unsigned int offA = 0u, offS = 0u;
    for (int w = 0; w < warp; ++w)     offA = max(offA, wA[w]);
    for (int w = warp + 1; w < 8; ++w) offS = max(offS, wS[w]);
    pv = max(pv, offA);
    sv = max(sv, offS);

    float c   = sC[tid];
    float dLo = pv ? (c - __uint_as_float(pv - 1u)) : FLT_MAX;
    float dHi = sv ? (__uint_as_float(~sv) - c)     : FLT_MAX;
    float d   = fminf(dLo, dHi);

#pragma unroll
    for (int o = 16; o >= 1; o >>= 1) d += __shfl_down_sync(0xffffffffu, d, o);
    if (lane == 0) wsum[warp] = d;
    __syncthreads();

    if (tid == 0) {
        float s = 0.0f;
        for (int w = 0; w < 8; ++w) s += wsum[w];
        g_batchSum[b] = s;

        __threadfence();
        unsigned int old = atomicAdd(&g_done, 1u);
        if (old == (unsigned)(B - 1)) {
            __threadfence();
            float tot = 0.0f;
            for (int i = 0; i < B; ++i) tot += g_batchSum[i];
            out[0] = tot;
            g_done = 0u;
        }
    }
}

extern "C" void kernel_launch(void* const* d_in, const int* in_sizes, int n_in,
                              void* d_out, int out_size)
{
    int bi = 0, di = 1;
    if (n_in >= 2 && in_sizes[0] > in_sizes[1]) { bi = 1; di = 0; }
    const float* bins  = (const float*)d_in[bi];
    const float* depth = (const float*)d_in[di];

    const int B = in_sizes[bi] / (P_BINS + 1);
    const int M = in_sizes[di] / B;

    dim3 grid(SPLITS, B);
    k_fused<<<grid, P_BINS>>>(bins, depth, M, B, (float*)d_out);
}